// round 12
// baseline (speedup 1.0000x reference)
#include <cuda_runtime.h>

#define NPTS    8192
#define BATCH   8
#define NPOINT  512
#define NSAMPLE 32
#define NT      (BATCH*NPOINT*NSAMPLE)   // 131072 samples
#define NSTILE  512                      // sample tiles of 256 in layer kernels

// ---------------- scratch (device globals; no allocation) ----------------
__device__ float g_X0[67u*NT];    // layer0 input features [c][t]
__device__ float g_Y0[64u*NT];    // layer0 raw output (pre-BN)
__device__ float g_Y1[64u*NT];    // layer1 raw output
__device__ float g_Y2[128u*NT];   // layer2 raw output
__device__ float g_newxyz[BATCH*NPOINT*3];   // (b,s,3) centroids
__device__ float g_psum[128*NSTILE];
__device__ float g_psq [128*NSTILE];
__device__ float g_scale[128];
__device__ float g_shift[128];

// ---------------- packed f32x2 helpers (per-half rounding == scalar ops) ---
typedef unsigned long long u64;
__device__ __forceinline__ u64 pk2(float lo, float hi) {
    u64 r; asm("mov.b64 %0,{%1,%2};" : "=l"(r) : "f"(lo), "f"(hi)); return r;
}
__device__ __forceinline__ void upk2(u64 v, float& lo, float& hi) {
    asm("mov.b64 {%0,%1},%2;" : "=f"(lo), "=f"(hi) : "l"(v));
}
__device__ __forceinline__ u64 add2(u64 a, u64 b) {
    u64 r; asm("add.rn.f32x2 %0,%1,%2;" : "=l"(r) : "l"(a), "l"(b)); return r;
}
__device__ __forceinline__ u64 mul2(u64 a, u64 b) {
    u64 r; asm("mul.rn.f32x2 %0,%1,%2;" : "=l"(r) : "l"(a), "l"(b)); return r;
}
__device__ __forceinline__ u64 fma2(u64 a, u64 b, u64 c) {
    u64 r; asm("fma.rn.f32x2 %0,%1,%2,%3;" : "=l"(r) : "l"(a), "l"(b), "l"(c)); return r;
}

// profiling alignment: ONE no-op so ncu's slot-6 capture = layer_kernel<64,true,1>
__global__ void nop_kernel() {}

// value-only butterfly max: every lane ends with the warp max
__device__ __forceinline__ float warp_fmax_bfly(float v) {
    #pragma unroll
    for (int off = 16; off; off >>= 1)
        v = fmaxf(v, __shfl_xor_sync(0xffffffffu, v, off));
    return v;
}
// 8-wide (input mirrored across quarter-warps)
__device__ __forceinline__ float warp_fmax_bfly8(float v) {
    #pragma unroll
    for (int off = 4; off; off >>= 1)
        v = fmaxf(v, __shfl_xor_sync(0xffffffffu, v, off));
    return v;
}

// ---------------- FPS (unchanged from round 11 — proven) ----------------
__global__ __launch_bounds__(256) void fps_kernel(const float* __restrict__ xyz,
                                                  float* __restrict__ out_newxyz)
{
    const int b    = blockIdx.x;
    const int tid  = threadIdx.x;
    const int lane = tid & 31;
    const int w    = tid >> 5;           // 0..7
    const float* X  = xyz + (size_t)b * 3 * NPTS;
    const float* Yc = X + NPTS;
    const float* Z  = X + 2 * NPTS;

    // load 32 contiguous points per thread (8x float4 per coordinate)
    float fx[32], fy[32], fz[32];
    #pragma unroll
    for (int r = 0; r < 8; r++) {
        float4 vx = reinterpret_cast<const float4*>(X )[tid * 8 + r];
        float4 vy = reinterpret_cast<const float4*>(Yc)[tid * 8 + r];
        float4 vz = reinterpret_cast<const float4*>(Z )[tid * 8 + r];
        fx[4*r+0]=vx.x; fx[4*r+1]=vx.y; fx[4*r+2]=vx.z; fx[4*r+3]=vx.w;
        fy[4*r+0]=vy.x; fy[4*r+1]=vy.y; fy[4*r+2]=vy.z; fy[4*r+3]=vy.w;
        fz[4*r+0]=vz.x; fz[4*r+1]=vz.y; fz[4*r+2]=vz.z; fz[4*r+3]=vz.w;
    }
    u64 px2[16], py2[16], pz2[16];
    float dist[32];
    #pragma unroll
    for (int m = 0; m < 16; m++) {
        px2[m] = pk2(fx[2*m], fx[2*m+1]);
        py2[m] = pk2(fy[2*m], fy[2*m+1]);
        pz2[m] = pk2(fz[2*m], fz[2*m+1]);
        dist[2*m] = 1e10f; dist[2*m+1] = 1e10f;
    }

    __shared__ float s_v[2][8];
    __shared__ int   s_i[2][8];

    // ---- init: far = argmax over x (first-index ties) ----
    int far;
    {
        float lv = fx[0];
        #pragma unroll
        for (int j = 1; j < 32; j++) lv = fmaxf(lv, fx[j]);
        unsigned mask = 0;
        #pragma unroll
        for (int j = 0; j < 32; j++)
            mask |= (fx[j] == lv) ? (1u << j) : 0u;
        int li = tid * 32 + (__ffs(mask) - 1);

        float wmax = warp_fmax_bfly(lv);
        unsigned wm = __ballot_sync(0xffffffffu, lv == wmax);
        if (lane == __ffs(wm) - 1) { s_v[1][w] = wmax; s_i[1][w] = li; }
        __syncthreads();
        float v2 = s_v[1][lane & 7];
        int   i2 = s_i[1][lane & 7];
        float bmax = warp_fmax_bfly8(v2);
        unsigned m2 = __ballot_sync(0xffffffffu, v2 == bmax);
        far = __shfl_sync(0xffffffffu, i2, __ffs(m2) - 1);
    }

    for (int s = 0; s < NPOINT; s++) {
        const float cx = X[far], cy = Yc[far], cz = Z[far];   // L1-resident
        if (tid == 0) {
            out_newxyz[(b * 3 + 0) * NPOINT + s] = cx;
            out_newxyz[(b * 3 + 1) * NPOINT + s] = cy;
            out_newxyz[(b * 3 + 2) * NPOINT + s] = cz;
            g_newxyz[(b * NPOINT + s) * 3 + 0] = cx;
            g_newxyz[(b * NPOINT + s) * 3 + 1] = cy;
            g_newxyz[(b * NPOINT + s) * 3 + 2] = cz;
        }
        const u64 ncx2 = pk2(-cx, -cx);
        const u64 ncy2 = pk2(-cy, -cy);
        const u64 ncz2 = pk2(-cz, -cz);
        #pragma unroll
        for (int m = 0; m < 16; m++) {
            u64 dx2 = add2(px2[m], ncx2);          // rn(px - cx) per half
            u64 dy2 = add2(py2[m], ncy2);
            u64 dz2 = add2(pz2[m], ncz2);
            u64 d2  = fma2(dz2, dz2, fma2(dy2, dy2, mul2(dx2, dx2)));
            float d0, d1; upk2(d2, d0, d1);
            dist[2*m]   = fminf(dist[2*m],   d0);
            dist[2*m+1] = fminf(dist[2*m+1], d1);
        }
        // local max (31-op tree) + first matching index via bitmask/ffs
        float lv;
        {
            float a[16];
            #pragma unroll
            for (int j = 0; j < 16; j++) a[j] = fmaxf(dist[2*j], dist[2*j+1]);
            float b0 = fmaxf(fmaxf(a[0], a[1]),  fmaxf(a[2], a[3]));
            float b1 = fmaxf(fmaxf(a[4], a[5]),  fmaxf(a[6], a[7]));
            float b2 = fmaxf(fmaxf(a[8], a[9]),  fmaxf(a[10], a[11]));
            float b3 = fmaxf(fmaxf(a[12], a[13]), fmaxf(a[14], a[15]));
            lv = fmaxf(fmaxf(b0, b1), fmaxf(b2, b3));
        }
        unsigned mask = 0;
        #pragma unroll
        for (int j = 0; j < 32; j++)
            mask |= (dist[j] == lv) ? (1u << j) : 0u;
        int li = tid * 32 + (__ffs(mask) - 1);

        // warp stage: value-only bfly + ballot; winning lane writes partials
        float wmax = warp_fmax_bfly(lv);
        unsigned wm = __ballot_sync(0xffffffffu, lv == wmax);
        const int p = s & 1;
        if (lane == __ffs(wm) - 1) { s_v[p][w] = wmax; s_i[p][w] = li; }
        __syncthreads();
        // block stage: all warps reduce the 8 partials (mirrored quarters)
        float v2 = s_v[p][lane & 7];
        int   i2 = s_i[p][lane & 7];
        float bmax = warp_fmax_bfly8(v2);
        unsigned m2 = __ballot_sync(0xffffffffu, v2 == bmax);
        far = __shfl_sync(0xffffffffu, i2, __ffs(m2) - 1);
    }
}

// ---------------- ball query + gather (one warp per (b,s)) ----------------
__global__ __launch_bounds__(256) void ball_gather_kernel(const float* __restrict__ xyz,
                                                          const float* __restrict__ points)
{
    const int w    = blockIdx.x * 8 + (threadIdx.x >> 5);
    const int lane = threadIdx.x & 31;
    const int b = w >> 9;
    const int s = w & 511;

    const float* X  = xyz + (size_t)b * 3 * NPTS;
    const float* Yc = X + NPTS;
    const float* Z  = X + 2 * NPTS;

    const float cx = g_newxyz[(b * NPOINT + s) * 3 + 0];
    const float cy = g_newxyz[(b * NPOINT + s) * 3 + 1];
    const float cz = g_newxyz[(b * NPOINT + s) * 3 + 2];
    const float cc = __fadd_rn(__fadd_rn(__fmul_rn(cx, cx), __fmul_rn(cy, cy)),
                               __fmul_rn(cz, cz));
    const float r2 = 0.04f;

    __shared__ int nbr_s[8][NSAMPLE];
    int* nbr = nbr_s[threadIdx.x >> 5];

    int found = 0;
    for (int base = 0; base < NPTS; base += 32) {
        int   j  = base + lane;
        float xj = X[j], yj = Yc[j], zj = Z[j];
        float dot = fmaf(cz, zj, fmaf(cy, yj, __fmul_rn(cx, xj)));
        float pp  = __fadd_rn(__fadd_rn(__fmul_rn(xj, xj), __fmul_rn(yj, yj)),
                              __fmul_rn(zj, zj));
        float d   = __fadd_rn(__fadd_rn(__fmul_rn(-2.0f, dot), cc), pp);
        bool in   = !(d > r2);
        unsigned m = __ballot_sync(0xffffffffu, in);
        int pos = found + __popc(m & ((1u << lane) - 1u));
        if (in && pos < NSAMPLE) nbr[pos] = j;
        found += __popc(m);
        if (found >= NSAMPLE) break;
    }
    __syncwarp();
    if (found > NSAMPLE) found = NSAMPLE;
    int j0 = nbr[0];
    int j  = (lane < found) ? nbr[lane] : j0;

    const int t = (b * NPOINT + s) * NSAMPLE + lane;
    g_X0[0u * NT + t] = X[j]  - cx;
    g_X0[1u * NT + t] = Yc[j] - cy;
    g_X0[2u * NT + t] = Z[j]  - cz;
    const float* P = points + (size_t)b * 64 * NPTS;
    #pragma unroll 4
    for (int d = 0; d < 64; d++) {
        g_X0[(size_t)(3 + d) * NT + t] = P[(size_t)d * NPTS + j];
    }
}

// ---------------- fused layer GEMM, f32x2-packed, pre-duplicated W --------
// Block = 256 threads. Tile = 256 samples x 64 outputs. Thread computes 4
// adjacent-sample pairs x 8 outputs via fma.rn.f32x2. Weights staged ONCE as
// duplicated (w,w) u64 in smem, so the inner loop is 4 LDS.64 (x) + 4
// broadcast LDS.128 (w) + 32 fma2 per cc (was 46 instr, now 40).
// CCH=8 keeps static smem under 48 KB (layer0: ~43 KB) at 2 CTAs/SM.
#define CCH 8
template<int CIN, bool BNIN, int LAYER>
__global__ __launch_bounds__(256, 2) void layer_kernel(const float* __restrict__ W,
                                                       const float* __restrict__ bias)
{
    const float* Xin  = (LAYER == 0) ? g_X0 : (LAYER == 1) ? g_Y0 : g_Y1;
    float*       Yout = (LAYER == 0) ? g_Y0 : (LAYER == 1) ? g_Y1 : g_Y2;

    __shared__ __align__(16) u64 WsT2[CIN * 64];   // [c][o], (w,w) duplicated
    __shared__ float bs2[64];
    __shared__ __align__(16) float Xs[CCH * 256];
    __shared__ float sc[CIN];
    __shared__ float sh[CIN];

    const int tid   = threadIdx.x;
    const int tx    = tid & 31;
    const int wp    = tid >> 5;
    const int obase = blockIdx.y * 64;
    const int tbase = blockIdx.x * 256;

    // stage W transposed + duplicated: WsT2[c*64+o] = (w,w)
    const float* Wg = W + (size_t)obase * CIN;
    for (int i = tid; i < 64 * CIN; i += 256) {
        int o = i & 63, c = i >> 6;
        float wv = Wg[o * CIN + c];
        WsT2[c * 64 + o] = pk2(wv, wv);
    }
    for (int i = tid; i < 64; i += 256) bs2[i] = bias[obase + i];
    if (BNIN) {
        for (int i = tid; i < CIN; i += 256) { sc[i] = g_scale[i]; sh[i] = g_shift[i]; }
    }
    __syncthreads();

    u64 acc2[4][8];
    #pragma unroll
    for (int j = 0; j < 8; j++) {
        float b0 = bs2[wp * 8 + j];
        u64 bb = pk2(b0, b0);
        #pragma unroll
        for (int k = 0; k < 4; k++) acc2[k][j] = bb;
    }

    for (int c0 = 0; c0 < CIN; c0 += CCH) {
        const int cn = (CIN - c0 < CCH) ? (CIN - c0) : CCH;
        __syncthreads();
        for (int e = tid; e < cn * 64; e += 256) {
            int cc   = e >> 6;
            int col4 = (e & 63) << 2;
            float4 v = *reinterpret_cast<const float4*>(
                Xin + (size_t)(c0 + cc) * NT + tbase + col4);
            if (BNIN) {
                float s = sc[c0 + cc], h = sh[c0 + cc];
                v.x = fmaxf(0.f, fmaf(v.x, s, h));
                v.y = fmaxf(0.f, fmaf(v.y, s, h));
                v.z = fmaxf(0.f, fmaf(v.z, s, h));
                v.w = fmaxf(0.f, fmaf(v.w, s, h));
            }
            *reinterpret_cast<float4*>(Xs + cc * 256 + col4) = v;
        }
        __syncthreads();
        for (int cc = 0; cc < cn; cc++) {
            u64 x2[4];
            #pragma unroll
            for (int k = 0; k < 4; k++)
                x2[k] = *reinterpret_cast<const u64*>(&Xs[cc * 256 + 64 * k + 2 * tx]);
            const ulonglong2* wrow = reinterpret_cast<const ulonglong2*>(
                &WsT2[(c0 + cc) * 64 + wp * 8]);
            ulonglong2 wa = wrow[0], wb = wrow[1], wc = wrow[2], wd = wrow[3];
            u64 w2[8] = {wa.x, wa.y, wb.x, wb.y, wc.x, wc.y, wd.x, wd.y};
            #pragma unroll
            for (int j = 0; j < 8; j++)
                #pragma unroll
                for (int k = 0; k < 4; k++)
                    acc2[k][j] = fma2(w2[j], x2[k], acc2[k][j]);
        }
    }

    #pragma unroll
    for (int j = 0; j < 8; j++) {
        const int o = obase + wp * 8 + j;
        float* yp = Yout + (size_t)o * NT + tbase + 2 * tx;
        #pragma unroll
        for (int k = 0; k < 4; k++)
            *reinterpret_cast<u64*>(yp + 64 * k) = acc2[k][j];
    }

    #pragma unroll
    for (int j = 0; j < 8; j++) {
        float s = 0.f, q = 0.f;
        #pragma unroll
        for (int k = 0; k < 4; k++) {
            float lo, hi; upk2(acc2[k][j], lo, hi);
            s += lo; s += hi;
            q = fmaf(lo, lo, q);
            q = fmaf(hi, hi, q);
        }
        #pragma unroll
        for (int off = 16; off; off >>= 1) {
            s += __shfl_down_sync(0xffffffffu, s, off);
            q += __shfl_down_sync(0xffffffffu, q, off);
        }
        if (tx == 0) {
            const int o = obase + wp * 8 + j;
            g_psum[o * NSTILE + blockIdx.x] = s;
            g_psq [o * NSTILE + blockIdx.x] = q;
        }
    }
}

// ---------------- reduce partials -> BN scale/shift (layers 0,1) ----------
__global__ __launch_bounds__(256) void finalize_kernel(const float* __restrict__ g,
                                                       const float* __restrict__ beta)
{
    const int c = blockIdx.x;
    float s = 0.f, q = 0.f;
    for (int i = threadIdx.x; i < NSTILE; i += 256) {
        s += g_psum[c * NSTILE + i];
        q += g_psq [c * NSTILE + i];
    }
    __shared__ float rs[8], rq[8];
    #pragma unroll
    for (int off = 16; off; off >>= 1) {
        s += __shfl_down_sync(0xffffffffu, s, off);
        q += __shfl_down_sync(0xffffffffu, q, off);
    }
    int w = threadIdx.x >> 5;
    if ((threadIdx.x & 31) == 0) { rs[w] = s; rq[w] = q; }
    __syncthreads();
    if (threadIdx.x == 0) {
        float ts = 0.f, tq = 0.f;
        #pragma unroll
        for (int i = 0; i < 8; i++) { ts += rs[i]; tq += rq[i]; }
        float mu  = ts * (1.0f / NT);
        float var = tq * (1.0f / NT) - mu * mu;
        float rsq = rsqrtf(var + 1e-5f);
        float scv = g[c] * rsq;
        g_scale[c] = scv;
        g_shift[c] = fmaf(-mu, scv, beta[c]);
    }
}

// ---------------- layer-2 BN finalize + BN + ReLU + max over k ------------
__global__ __launch_bounds__(256) void final_kernel(float* __restrict__ out2,
                                                    const float* __restrict__ g,
                                                    const float* __restrict__ beta)
{
    const int bo = blockIdx.x;
    const int b = bo >> 7;
    const int o = bo & 127;
    const int tid  = threadIdx.x;
    const int w    = tid >> 5;
    const int lane = tid & 31;

    __shared__ float rs[8], rq[8];
    __shared__ float s_sc, s_sh;
    {
        float s = 0.f, q = 0.f;
        for (int i = tid; i < NSTILE; i += 256) {
            s += g_psum[o * NSTILE + i];
            q += g_psq [o * NSTILE + i];
        }
        #pragma unroll
        for (int off = 16; off; off >>= 1) {
            s += __shfl_down_sync(0xffffffffu, s, off);
            q += __shfl_down_sync(0xffffffffu, q, off);
        }
        if (lane == 0) { rs[w] = s; rq[w] = q; }
        __syncthreads();
        if (tid == 0) {
            float ts = 0.f, tq = 0.f;
            #pragma unroll
            for (int i = 0; i < 8; i++) { ts += rs[i]; tq += rq[i]; }
            float mu  = ts * (1.0f / NT);
            float var = tq * (1.0f / NT) - mu * mu;
            float rsq = rsqrtf(var + 1e-5f);
            float scv = g[o] * rsq;
            s_sc = scv;
            s_sh = fmaf(-mu, scv, beta[o]);
        }
        __syncthreads();
    }
    const float scv = s_sc;
    const float shv = s_sh;

    const float* p = g_Y2 + (size_t)o * NT + (size_t)b * (NPOINT * NSAMPLE);
    for (int r = 0; r < 64; r++) {
        float v = p[tid + r * 256];
        v = fmaxf(0.f, fmaf(v, scv, shv));
        #pragma unroll
        for (int off = 16; off; off >>= 1)
            v = fmaxf(v, __shfl_down_sync(0xffffffffu, v, off));
        if (lane == 0)
            out2[(b * 128 + o) * NPOINT + (w + 8 * r)] = v;
    }
}

// ---------------- launch ----------------
extern "C" void kernel_launch(void* const* d_in, const int* in_sizes, int n_in,
                              void* d_out, int out_size)
{
    (void)in_sizes; (void)n_in; (void)out_size;
    const float* xyz    = (const float*)d_in[0];
    const float* points = (const float*)d_in[1];
    const float* W0 = (const float*)d_in[2];
    const float* b0 = (const float*)d_in[3];
    const float* g0 = (const float*)d_in[4];
    const float* be0= (const float*)d_in[5];
    const float* W1 = (const float*)d_in[6];
    const float* b1 = (const float*)d_in[7];
    const float* g1 = (const float*)d_in[8];
    const float* be1= (const float*)d_in[9];
    const float* W2 = (const float*)d_in[10];
    const float* b2 = (const float*)d_in[11];
    const float* g2 = (const float*)d_in[12];
    const float* be2= (const float*)d_in[13];

    float* out = (float*)d_out;

    // ncu slot-6 alignment: launches are nop(1), fps(2), ball(3), L0(4),
    // fin0(5), L1(6)  -> profile captures layer_kernel<64,true,1>
    nop_kernel<<<1, 1>>>();

    fps_kernel<<<BATCH, 256>>>(xyz, out);
    ball_gather_kernel<<<(BATCH * NPOINT) / 8, 256>>>(xyz, points);

    layer_kernel<67, false, 0><<<dim3(NSTILE, 1), 256>>>(W0, b0);
    finalize_kernel<<<64, 256>>>(g0, be0);

    layer_kernel<64, true, 1><<<dim3(NSTILE, 1), 256>>>(W1, b1);
    finalize_kernel<<<64, 256>>>(g1, be1);

    layer_kernel<64, true, 2><<<dim3(NSTILE, 2), 256>>>(W2, b2);

    final_kernel<<<BATCH * 128, 256>>>(out + BATCH * 3 * NPOINT, g2, be2);
}

// round 14
// speedup vs baseline: 1.0276x; 1.0276x over previous
#include <cuda_runtime.h>

#define NPTS    8192
#define BATCH   8
#define NPOINT  512
#define NSAMPLE 32
#define NT      (BATCH*NPOINT*NSAMPLE)   // 131072 samples
#define NSTILE  512                      // sample tiles of 256 in layer kernels

// ---------------- scratch (device globals; no allocation) ----------------
__device__ float g_X0[67u*NT];    // layer0 input features [c][t]
__device__ float g_Y0[64u*NT];    // layer0 raw output (pre-BN)
__device__ float g_Y1[64u*NT];    // layer1 raw output
__device__ float g_Y2[128u*NT];   // layer2 raw output
__device__ float g_newxyz[BATCH*NPOINT*3];   // (b,s,3) centroids
__device__ float g_psum[128*NSTILE];
__device__ float g_psq [128*NSTILE];
__device__ float g_scale[128];
__device__ float g_shift[128];

// ---------------- packed f32x2 helpers (per-half rounding == scalar ops) ---
typedef unsigned long long u64;
__device__ __forceinline__ u64 pk2(float lo, float hi) {
    u64 r; asm("mov.b64 %0,{%1,%2};" : "=l"(r) : "f"(lo), "f"(hi)); return r;
}
__device__ __forceinline__ void upk2(u64 v, float& lo, float& hi) {
    asm("mov.b64 {%0,%1},%2;" : "=f"(lo), "=f"(hi) : "l"(v));
}
__device__ __forceinline__ u64 add2(u64 a, u64 b) {
    u64 r; asm("add.rn.f32x2 %0,%1,%2;" : "=l"(r) : "l"(a), "l"(b)); return r;
}
__device__ __forceinline__ u64 mul2(u64 a, u64 b) {
    u64 r; asm("mul.rn.f32x2 %0,%1,%2;" : "=l"(r) : "l"(a), "l"(b)); return r;
}
__device__ __forceinline__ u64 fma2(u64 a, u64 b, u64 c) {
    u64 r; asm("fma.rn.f32x2 %0,%1,%2,%3;" : "=l"(r) : "l"(a), "l"(b), "l"(c)); return r;
}

// value-only butterfly max: every lane ends with the warp max
__device__ __forceinline__ float warp_fmax_bfly(float v) {
    #pragma unroll
    for (int off = 16; off; off >>= 1)
        v = fmaxf(v, __shfl_xor_sync(0xffffffffu, v, off));
    return v;
}
// 8-wide (input mirrored across quarter-warps)
__device__ __forceinline__ float warp_fmax_bfly8(float v) {
    #pragma unroll
    for (int off = 4; off; off >>= 1)
        v = fmaxf(v, __shfl_xor_sync(0xffffffffu, v, off));
    return v;
}

// ---------------- FPS (unchanged from round 11 — proven) ----------------
__global__ __launch_bounds__(256) void fps_kernel(const float* __restrict__ xyz,
                                                  float* __restrict__ out_newxyz)
{
    const int b    = blockIdx.x;
    const int tid  = threadIdx.x;
    const int lane = tid & 31;
    const int w    = tid >> 5;           // 0..7
    const float* X  = xyz + (size_t)b * 3 * NPTS;
    const float* Yc = X + NPTS;
    const float* Z  = X + 2 * NPTS;

    // load 32 contiguous points per thread (8x float4 per coordinate)
    float fx[32], fy[32], fz[32];
    #pragma unroll
    for (int r = 0; r < 8; r++) {
        float4 vx = reinterpret_cast<const float4*>(X )[tid * 8 + r];
        float4 vy = reinterpret_cast<const float4*>(Yc)[tid * 8 + r];
        float4 vz = reinterpret_cast<const float4*>(Z )[tid * 8 + r];
        fx[4*r+0]=vx.x; fx[4*r+1]=vx.y; fx[4*r+2]=vx.z; fx[4*r+3]=vx.w;
        fy[4*r+0]=vy.x; fy[4*r+1]=vy.y; fy[4*r+2]=vy.z; fy[4*r+3]=vy.w;
        fz[4*r+0]=vz.x; fz[4*r+1]=vz.y; fz[4*r+2]=vz.z; fz[4*r+3]=vz.w;
    }
    u64 px2[16], py2[16], pz2[16];
    float dist[32];
    #pragma unroll
    for (int m = 0; m < 16; m++) {
        px2[m] = pk2(fx[2*m], fx[2*m+1]);
        py2[m] = pk2(fy[2*m], fy[2*m+1]);
        pz2[m] = pk2(fz[2*m], fz[2*m+1]);
        dist[2*m] = 1e10f; dist[2*m+1] = 1e10f;
    }

    __shared__ float s_v[2][8];
    __shared__ int   s_i[2][8];

    // ---- init: far = argmax over x (first-index ties) ----
    int far;
    {
        float lv = fx[0];
        #pragma unroll
        for (int j = 1; j < 32; j++) lv = fmaxf(lv, fx[j]);
        unsigned mask = 0;
        #pragma unroll
        for (int j = 0; j < 32; j++)
            mask |= (fx[j] == lv) ? (1u << j) : 0u;
        int li = tid * 32 + (__ffs(mask) - 1);

        float wmax = warp_fmax_bfly(lv);
        unsigned wm = __ballot_sync(0xffffffffu, lv == wmax);
        if (lane == __ffs(wm) - 1) { s_v[1][w] = wmax; s_i[1][w] = li; }
        __syncthreads();
        float v2 = s_v[1][lane & 7];
        int   i2 = s_i[1][lane & 7];
        float bmax = warp_fmax_bfly8(v2);
        unsigned m2 = __ballot_sync(0xffffffffu, v2 == bmax);
        far = __shfl_sync(0xffffffffu, i2, __ffs(m2) - 1);
    }

    for (int s = 0; s < NPOINT; s++) {
        const float cx = X[far], cy = Yc[far], cz = Z[far];   // L1-resident
        if (tid == 0) {
            out_newxyz[(b * 3 + 0) * NPOINT + s] = cx;
            out_newxyz[(b * 3 + 1) * NPOINT + s] = cy;
            out_newxyz[(b * 3 + 2) * NPOINT + s] = cz;
            g_newxyz[(b * NPOINT + s) * 3 + 0] = cx;
            g_newxyz[(b * NPOINT + s) * 3 + 1] = cy;
            g_newxyz[(b * NPOINT + s) * 3 + 2] = cz;
        }
        const u64 ncx2 = pk2(-cx, -cx);
        const u64 ncy2 = pk2(-cy, -cy);
        const u64 ncz2 = pk2(-cz, -cz);
        #pragma unroll
        for (int m = 0; m < 16; m++) {
            u64 dx2 = add2(px2[m], ncx2);          // rn(px - cx) per half
            u64 dy2 = add2(py2[m], ncy2);
            u64 dz2 = add2(pz2[m], ncz2);
            u64 d2  = fma2(dz2, dz2, fma2(dy2, dy2, mul2(dx2, dx2)));
            float d0, d1; upk2(d2, d0, d1);
            dist[2*m]   = fminf(dist[2*m],   d0);
            dist[2*m+1] = fminf(dist[2*m+1], d1);
        }
        // local max (31-op tree) + first matching index via bitmask/ffs
        float lv;
        {
            float a[16];
            #pragma unroll
            for (int j = 0; j < 16; j++) a[j] = fmaxf(dist[2*j], dist[2*j+1]);
            float b0 = fmaxf(fmaxf(a[0], a[1]),  fmaxf(a[2], a[3]));
            float b1 = fmaxf(fmaxf(a[4], a[5]),  fmaxf(a[6], a[7]));
            float b2 = fmaxf(fmaxf(a[8], a[9]),  fmaxf(a[10], a[11]));
            float b3 = fmaxf(fmaxf(a[12], a[13]), fmaxf(a[14], a[15]));
            lv = fmaxf(fmaxf(b0, b1), fmaxf(b2, b3));
        }
        unsigned mask = 0;
        #pragma unroll
        for (int j = 0; j < 32; j++)
            mask |= (dist[j] == lv) ? (1u << j) : 0u;
        int li = tid * 32 + (__ffs(mask) - 1);

        // warp stage: value-only bfly + ballot; winning lane writes partials
        float wmax = warp_fmax_bfly(lv);
        unsigned wm = __ballot_sync(0xffffffffu, lv == wmax);
        const int p = s & 1;
        if (lane == __ffs(wm) - 1) { s_v[p][w] = wmax; s_i[p][w] = li; }
        __syncthreads();
        // block stage: all warps reduce the 8 partials (mirrored quarters)
        float v2 = s_v[p][lane & 7];
        int   i2 = s_i[p][lane & 7];
        float bmax = warp_fmax_bfly8(v2);
        unsigned m2 = __ballot_sync(0xffffffffu, v2 == bmax);
        far = __shfl_sync(0xffffffffu, i2, __ffs(m2) - 1);
    }
}

// ---------------- ball query + gather (one warp per (b,s)) ----------------
__global__ __launch_bounds__(256) void ball_gather_kernel(const float* __restrict__ xyz,
                                                          const float* __restrict__ points)
{
    const int w    = blockIdx.x * 8 + (threadIdx.x >> 5);
    const int lane = threadIdx.x & 31;
    const int b = w >> 9;
    const int s = w & 511;

    const float* X  = xyz + (size_t)b * 3 * NPTS;
    const float* Yc = X + NPTS;
    const float* Z  = X + 2 * NPTS;

    const float cx = g_newxyz[(b * NPOINT + s) * 3 + 0];
    const float cy = g_newxyz[(b * NPOINT + s) * 3 + 1];
    const float cz = g_newxyz[(b * NPOINT + s) * 3 + 2];
    const float cc = __fadd_rn(__fadd_rn(__fmul_rn(cx, cx), __fmul_rn(cy, cy)),
                               __fmul_rn(cz, cz));
    const float r2 = 0.04f;

    __shared__ int nbr_s[8][NSAMPLE];
    int* nbr = nbr_s[threadIdx.x >> 5];

    int found = 0;
    for (int base = 0; base < NPTS; base += 32) {
        int   j  = base + lane;
        float xj = X[j], yj = Yc[j], zj = Z[j];
        float dot = fmaf(cz, zj, fmaf(cy, yj, __fmul_rn(cx, xj)));
        float pp  = __fadd_rn(__fadd_rn(__fmul_rn(xj, xj), __fmul_rn(yj, yj)),
                              __fmul_rn(zj, zj));
        float d   = __fadd_rn(__fadd_rn(__fmul_rn(-2.0f, dot), cc), pp);
        bool in   = !(d > r2);
        unsigned m = __ballot_sync(0xffffffffu, in);
        int pos = found + __popc(m & ((1u << lane) - 1u));
        if (in && pos < NSAMPLE) nbr[pos] = j;
        found += __popc(m);
        if (found >= NSAMPLE) break;
    }
    __syncwarp();
    if (found > NSAMPLE) found = NSAMPLE;
    int j0 = nbr[0];
    int j  = (lane < found) ? nbr[lane] : j0;

    const int t = (b * NPOINT + s) * NSAMPLE + lane;
    g_X0[0u * NT + t] = X[j]  - cx;
    g_X0[1u * NT + t] = Yc[j] - cy;
    g_X0[2u * NT + t] = Z[j]  - cz;
    const float* P = points + (size_t)b * 64 * NPTS;
    #pragma unroll 4
    for (int d = 0; d < 64; d++) {
        g_X0[(size_t)(3 + d) * NT + t] = P[(size_t)d * NPTS + j];
    }
}

// ---------------- fused layer GEMM: f32x2, DOUBLE-BUFFERED staging --------
// Block = 256 threads. Tile = 256 samples x 64 outputs. Thread computes 4
// adjacent-sample pairs x 8 outputs via fma.rn.f32x2 (per-half rounding ==
// scalar FFMA). X staged through a 2-deep smem ring: stage chunk i+1 while
// computing chunk i, one barrier per chunk. RACE FIX vs round 13: a barrier
// after the cooperative WsT/bs2/sc/sh staging, BEFORE the prologue stage(0)
// and accumulator init consume sc/sh/bs2 written by other threads.
#define CCH 12
template<int CIN, bool BNIN, int LAYER>
__global__ __launch_bounds__(256, 2) void layer_kernel(const float* __restrict__ W,
                                                       const float* __restrict__ bias)
{
    const float* Xin  = (LAYER == 0) ? g_X0 : (LAYER == 1) ? g_Y0 : g_Y1;
    float*       Yout = (LAYER == 0) ? g_Y0 : (LAYER == 1) ? g_Y1 : g_Y2;

    __shared__ __align__(16) float WsT[CIN * 64];       // [c][o]
    __shared__ float bs2[64];
    __shared__ __align__(16) float Xs[2][CCH * 256];    // double buffer
    __shared__ float sc[CIN];
    __shared__ float sh[CIN];

    const int tid   = threadIdx.x;
    const int tx    = tid & 31;
    const int wp    = tid >> 5;
    const int obase = blockIdx.y * 64;
    const int tbase = blockIdx.x * 256;

    const float* Wg = W + (size_t)obase * CIN;
    for (int i = tid; i < 64 * CIN; i += 256) {
        int o = i & 63, c = i >> 6;
        WsT[c * 64 + o] = Wg[o * CIN + c];
    }
    for (int i = tid; i < 64; i += 256) bs2[i] = bias[obase + i];
    if (BNIN) {
        for (int i = tid; i < CIN; i += 256) { sc[i] = g_scale[i]; sh[i] = g_shift[i]; }
    }
    __syncthreads();   // RACE FIX: sc/sh/bs2/WsT visible before any consumer

    u64 acc2[4][8];

    // stage chunk starting at channel cbase (count cn) into buffer buf
    auto stage = [&](int cbase, int cn, float* buf) {
        for (int e = tid; e < cn * 64; e += 256) {
            int cc   = e >> 6;
            int col4 = (e & 63) << 2;
            float4 v = *reinterpret_cast<const float4*>(
                Xin + (size_t)(cbase + cc) * NT + tbase + col4);
            if (BNIN) {
                float s = sc[cbase + cc], h = sh[cbase + cc];
                v.x = fmaxf(0.f, fmaf(v.x, s, h));
                v.y = fmaxf(0.f, fmaf(v.y, s, h));
                v.z = fmaxf(0.f, fmaf(v.z, s, h));
                v.w = fmaxf(0.f, fmaf(v.w, s, h));
            }
            *reinterpret_cast<float4*>(buf + cc * 256 + col4) = v;
        }
    };

    // prologue: stage chunk 0 + init accumulators, then one barrier
    {
        int cn0 = (CIN < CCH) ? CIN : CCH;
        stage(0, cn0, Xs[0]);
    }
    #pragma unroll
    for (int j = 0; j < 8; j++) {
        float b0 = bs2[wp * 8 + j];
        u64 bb = pk2(b0, b0);
        #pragma unroll
        for (int k = 0; k < 4; k++) acc2[k][j] = bb;
    }
    __syncthreads();   // Xs[0] staged by all threads

    int ib = 0;
    for (int c0 = 0; c0 < CIN; c0 += CCH, ib ^= 1) {
        const int cn = (CIN - c0 < CCH) ? (CIN - c0) : CCH;
        // stage next chunk into the other buffer (overlaps with compute)
        if (c0 + CCH < CIN) {
            int cn1 = (CIN - c0 - CCH < CCH) ? (CIN - c0 - CCH) : CCH;
            stage(c0 + CCH, cn1, Xs[ib ^ 1]);
        }
        // compute current chunk from buffer ib
        const float* xb = Xs[ib];
        for (int cc = 0; cc < cn; cc++) {
            u64 x2[4];
            #pragma unroll
            for (int k = 0; k < 4; k++)
                x2[k] = *reinterpret_cast<const u64*>(&xb[cc * 256 + 64 * k + 2 * tx]);
            float4 wA = *reinterpret_cast<const float4*>(&WsT[(c0 + cc) * 64 + wp * 8]);
            float4 wB = *reinterpret_cast<const float4*>(&WsT[(c0 + cc) * 64 + wp * 8 + 4]);
            u64 w2[8] = {pk2(wA.x, wA.x), pk2(wA.y, wA.y), pk2(wA.z, wA.z), pk2(wA.w, wA.w),
                         pk2(wB.x, wB.x), pk2(wB.y, wB.y), pk2(wB.z, wB.z), pk2(wB.w, wB.w)};
            #pragma unroll
            for (int j = 0; j < 8; j++)
                #pragma unroll
                for (int k = 0; k < 4; k++)
                    acc2[k][j] = fma2(w2[j], x2[k], acc2[k][j]);
        }
        __syncthreads();   // next buffer fully staged; current reusable
    }

    #pragma unroll
    for (int j = 0; j < 8; j++) {
        const int o = obase + wp * 8 + j;
        float* yp = Yout + (size_t)o * NT + tbase + 2 * tx;
        #pragma unroll
        for (int k = 0; k < 4; k++)
            *reinterpret_cast<u64*>(yp + 64 * k) = acc2[k][j];
    }

    #pragma unroll
    for (int j = 0; j < 8; j++) {
        float s = 0.f, q = 0.f;
        #pragma unroll
        for (int k = 0; k < 4; k++) {
            float lo, hi; upk2(acc2[k][j], lo, hi);
            s += lo; s += hi;
            q = fmaf(lo, lo, q);
            q = fmaf(hi, hi, q);
        }
        #pragma unroll
        for (int off = 16; off; off >>= 1) {
            s += __shfl_down_sync(0xffffffffu, s, off);
            q += __shfl_down_sync(0xffffffffu, q, off);
        }
        if (tx == 0) {
            const int o = obase + wp * 8 + j;
            g_psum[o * NSTILE + blockIdx.x] = s;
            g_psq [o * NSTILE + blockIdx.x] = q;
        }
    }
}

// ---------------- reduce partials -> BN scale/shift (layers 0,1) ----------
__global__ __launch_bounds__(256) void finalize_kernel(const float* __restrict__ g,
                                                       const float* __restrict__ beta)
{
    const int c = blockIdx.x;
    float s = 0.f, q = 0.f;
    for (int i = threadIdx.x; i < NSTILE; i += 256) {
        s += g_psum[c * NSTILE + i];
        q += g_psq [c * NSTILE + i];
    }
    __shared__ float rs[8], rq[8];
    #pragma unroll
    for (int off = 16; off; off >>= 1) {
        s += __shfl_down_sync(0xffffffffu, s, off);
        q += __shfl_down_sync(0xffffffffu, q, off);
    }
    int w = threadIdx.x >> 5;
    if ((threadIdx.x & 31) == 0) { rs[w] = s; rq[w] = q; }
    __syncthreads();
    if (threadIdx.x == 0) {
        float ts = 0.f, tq = 0.f;
        #pragma unroll
        for (int i = 0; i < 8; i++) { ts += rs[i]; tq += rq[i]; }
        float mu  = ts * (1.0f / NT);
        float var = tq * (1.0f / NT) - mu * mu;
        float rsq = rsqrtf(var + 1e-5f);
        float scv = g[c] * rsq;
        g_scale[c] = scv;
        g_shift[c] = fmaf(-mu, scv, beta[c]);
    }
}

// ---------------- layer-2 BN finalize + BN + ReLU + max over k ------------
__global__ __launch_bounds__(256) void final_kernel(float* __restrict__ out2,
                                                    const float* __restrict__ g,
                                                    const float* __restrict__ beta)
{
    const int bo = blockIdx.x;
    const int b = bo >> 7;
    const int o = bo & 127;
    const int tid  = threadIdx.x;
    const int w    = tid >> 5;
    const int lane = tid & 31;

    __shared__ float rs[8], rq[8];
    __shared__ float s_sc, s_sh;
    {
        float s = 0.f, q = 0.f;
        for (int i = tid; i < NSTILE; i += 256) {
            s += g_psum[o * NSTILE + i];
            q += g_psq [o * NSTILE + i];
        }
        #pragma unroll
        for (int off = 16; off; off >>= 1) {
            s += __shfl_down_sync(0xffffffffu, s, off);
            q += __shfl_down_sync(0xffffffffu, q, off);
        }
        if (lane == 0) { rs[w] = s; rq[w] = q; }
        __syncthreads();
        if (tid == 0) {
            float ts = 0.f, tq = 0.f;
            #pragma unroll
            for (int i = 0; i < 8; i++) { ts += rs[i]; tq += rq[i]; }
            float mu  = ts * (1.0f / NT);
            float var = tq * (1.0f / NT) - mu * mu;
            float rsq = rsqrtf(var + 1e-5f);
            float scv = g[o] * rsq;
            s_sc = scv;
            s_sh = fmaf(-mu, scv, beta[o]);
        }
        __syncthreads();
    }
    const float scv = s_sc;
    const float shv = s_sh;

    const float* p = g_Y2 + (size_t)o * NT + (size_t)b * (NPOINT * NSAMPLE);
    for (int r = 0; r < 64; r++) {
        float v = p[tid + r * 256];
        v = fmaxf(0.f, fmaf(v, scv, shv));
        #pragma unroll
        for (int off = 16; off; off >>= 1)
            v = fmaxf(v, __shfl_down_sync(0xffffffffu, v, off));
        if (lane == 0)
            out2[(b * 128 + o) * NPOINT + (w + 8 * r)] = v;
    }
}

// ---------------- launch ----------------
extern "C" void kernel_launch(void* const* d_in, const int* in_sizes, int n_in,
                              void* d_out, int out_size)
{
    (void)in_sizes; (void)n_in; (void)out_size;
    const float* xyz    = (const float*)d_in[0];
    const float* points = (const float*)d_in[1];
    const float* W0 = (const float*)d_in[2];
    const float* b0 = (const float*)d_in[3];
    const float* g0 = (const float*)d_in[4];
    const float* be0= (const float*)d_in[5];
    const float* W1 = (const float*)d_in[6];
    const float* b1 = (const float*)d_in[7];
    const float* g1 = (const float*)d_in[8];
    const float* be1= (const float*)d_in[9];
    const float* W2 = (const float*)d_in[10];
    const float* b2 = (const float*)d_in[11];
    const float* g2 = (const float*)d_in[12];
    const float* be2= (const float*)d_in[13];

    float* out = (float*)d_out;

    fps_kernel<<<BATCH, 256>>>(xyz, out);
    ball_gather_kernel<<<(BATCH * NPOINT) / 8, 256>>>(xyz, points);

    layer_kernel<67, false, 0><<<dim3(NSTILE, 1), 256>>>(W0, b0);
    finalize_kernel<<<64, 256>>>(g0, be0);

    layer_kernel<64, true, 1><<<dim3(NSTILE, 1), 256>>>(W1, b1);
    finalize_kernel<<<64, 256>>>(g1, be1);

    layer_kernel<64, true, 2><<<dim3(NSTILE, 2), 256>>>(W2, b2);

    final_kernel<<<BATCH * 128, 256>>>(out + BATCH * 3 * NPOINT, g2, be2);
}

// round 15
// speedup vs baseline: 1.0748x; 1.0460x over previous
#include <cuda_runtime.h>

#define NPTS    8192
#define BATCH   8
#define NPOINT  512
#define NSAMPLE 32
#define NT      (BATCH*NPOINT*NSAMPLE)   // 131072 samples
#define NSTILE  512                      // sample tiles of 256 in layer kernels

// ---------------- scratch (device globals; no allocation) ----------------
__device__ float g_X0[67u*NT];    // layer0 input features [c][t]
__device__ float g_Y0[64u*NT];    // layer0 raw output (pre-BN)
__device__ float g_Y1[64u*NT];    // layer1 raw output
__device__ float g_Y2[128u*NT];   // layer2 raw output
__device__ float g_newxyz[BATCH*NPOINT*3];   // (b,s,3) centroids
__device__ float g_psum[128*NSTILE];
__device__ float g_psq [128*NSTILE];
__device__ float g_scale[128];
__device__ float g_shift[128];

// ---------------- packed f32x2 helpers (per-half rounding == scalar ops) ---
typedef unsigned long long u64;
__device__ __forceinline__ u64 pk2(float lo, float hi) {
    u64 r; asm("mov.b64 %0,{%1,%2};" : "=l"(r) : "f"(lo), "f"(hi)); return r;
}
__device__ __forceinline__ void upk2(u64 v, float& lo, float& hi) {
    asm("mov.b64 {%0,%1},%2;" : "=f"(lo), "=f"(hi) : "l"(v));
}
__device__ __forceinline__ u64 add2(u64 a, u64 b) {
    u64 r; asm("add.rn.f32x2 %0,%1,%2;" : "=l"(r) : "l"(a), "l"(b)); return r;
}
__device__ __forceinline__ u64 mul2(u64 a, u64 b) {
    u64 r; asm("mul.rn.f32x2 %0,%1,%2;" : "=l"(r) : "l"(a), "l"(b)); return r;
}
__device__ __forceinline__ u64 fma2(u64 a, u64 b, u64 c) {
    u64 r; asm("fma.rn.f32x2 %0,%1,%2,%3;" : "=l"(r) : "l"(a), "l"(b), "l"(c)); return r;
}

// ---------------- FPS ----------------
// One CTA per batch, 256 threads (8 warps), 32 contiguous points/thread.
// Value reduction via __reduce_max_sync on float bits (nonneg -> u32
// monotone; EXACT), first-index via ballot/ffs (verified rounds 10/11).
// Only 2 redux per warp per iter x 8 warps = 16 atom-unit ops (round-4's
// regression was 128/iter); replaces ~240 cyc of dependent SHFL chain.
__global__ __launch_bounds__(256) void fps_kernel(const float* __restrict__ xyz,
                                                  float* __restrict__ out_newxyz)
{
    const int b    = blockIdx.x;
    const int tid  = threadIdx.x;
    const int lane = tid & 31;
    const int w    = tid >> 5;           // 0..7
    const float* X  = xyz + (size_t)b * 3 * NPTS;
    const float* Yc = X + NPTS;
    const float* Z  = X + 2 * NPTS;

    // load 32 contiguous points per thread (8x float4 per coordinate)
    float fx[32], fy[32], fz[32];
    #pragma unroll
    for (int r = 0; r < 8; r++) {
        float4 vx = reinterpret_cast<const float4*>(X )[tid * 8 + r];
        float4 vy = reinterpret_cast<const float4*>(Yc)[tid * 8 + r];
        float4 vz = reinterpret_cast<const float4*>(Z )[tid * 8 + r];
        fx[4*r+0]=vx.x; fx[4*r+1]=vx.y; fx[4*r+2]=vx.z; fx[4*r+3]=vx.w;
        fy[4*r+0]=vy.x; fy[4*r+1]=vy.y; fy[4*r+2]=vy.z; fy[4*r+3]=vy.w;
        fz[4*r+0]=vz.x; fz[4*r+1]=vz.y; fz[4*r+2]=vz.z; fz[4*r+3]=vz.w;
    }
    u64 px2[16], py2[16], pz2[16];
    float dist[32];
    #pragma unroll
    for (int m = 0; m < 16; m++) {
        px2[m] = pk2(fx[2*m], fx[2*m+1]);
        py2[m] = pk2(fy[2*m], fy[2*m+1]);
        pz2[m] = pk2(fz[2*m], fz[2*m+1]);
        dist[2*m] = 1e10f; dist[2*m+1] = 1e10f;
    }

    __shared__ float s_v[2][8];
    __shared__ int   s_i[2][8];

    // ---- init: far = argmax over x (first-index ties). x in [0,1) ----
    int far;
    {
        float lv = fx[0];
        #pragma unroll
        for (int j = 1; j < 32; j++) lv = fmaxf(lv, fx[j]);
        unsigned mask = 0;
        #pragma unroll
        for (int j = 0; j < 32; j++)
            mask |= (fx[j] == lv) ? (1u << j) : 0u;
        int li = tid * 32 + (__ffs(mask) - 1);

        unsigned wmax = __reduce_max_sync(0xffffffffu, __float_as_uint(lv));
        unsigned wm = __ballot_sync(0xffffffffu, __float_as_uint(lv) == wmax);
        if (lane == __ffs(wm) - 1) { s_v[1][w] = __uint_as_float(wmax); s_i[1][w] = li; }
        __syncthreads();
        float v2 = s_v[1][lane & 7];
        int   i2 = s_i[1][lane & 7];
        unsigned bmax = __reduce_max_sync(0xffffffffu, __float_as_uint(v2));
        unsigned m2 = __ballot_sync(0xffffffffu, __float_as_uint(v2) == bmax);
        far = __shfl_sync(0xffffffffu, i2, __ffs(m2) - 1);
    }

    for (int s = 0; s < NPOINT; s++) {
        const float cx = X[far], cy = Yc[far], cz = Z[far];   // L1-resident
        if (tid == 0) {
            out_newxyz[(b * 3 + 0) * NPOINT + s] = cx;
            out_newxyz[(b * 3 + 1) * NPOINT + s] = cy;
            out_newxyz[(b * 3 + 2) * NPOINT + s] = cz;
            g_newxyz[(b * NPOINT + s) * 3 + 0] = cx;
            g_newxyz[(b * NPOINT + s) * 3 + 1] = cy;
            g_newxyz[(b * NPOINT + s) * 3 + 2] = cz;
        }
        const u64 ncx2 = pk2(-cx, -cx);
        const u64 ncy2 = pk2(-cy, -cy);
        const u64 ncz2 = pk2(-cz, -cz);
        #pragma unroll
        for (int m = 0; m < 16; m++) {
            u64 dx2 = add2(px2[m], ncx2);          // rn(px - cx) per half
            u64 dy2 = add2(py2[m], ncy2);
            u64 dz2 = add2(pz2[m], ncz2);
            u64 d2  = fma2(dz2, dz2, fma2(dy2, dy2, mul2(dx2, dx2)));
            float d0, d1; upk2(d2, d0, d1);
            dist[2*m]   = fminf(dist[2*m],   d0);
            dist[2*m+1] = fminf(dist[2*m+1], d1);
        }
        // local max (31-op tree) + first matching index via bitmask/ffs
        float lv;
        {
            float a[16];
            #pragma unroll
            for (int j = 0; j < 16; j++) a[j] = fmaxf(dist[2*j], dist[2*j+1]);
            float b0 = fmaxf(fmaxf(a[0], a[1]),  fmaxf(a[2], a[3]));
            float b1 = fmaxf(fmaxf(a[4], a[5]),  fmaxf(a[6], a[7]));
            float b2 = fmaxf(fmaxf(a[8], a[9]),  fmaxf(a[10], a[11]));
            float b3 = fmaxf(fmaxf(a[12], a[13]), fmaxf(a[14], a[15]));
            lv = fmaxf(fmaxf(b0, b1), fmaxf(b2, b3));
        }
        unsigned mask = 0;
        #pragma unroll
        for (int j = 0; j < 32; j++)
            mask |= (dist[j] == lv) ? (1u << j) : 0u;
        int li = tid * 32 + (__ffs(mask) - 1);

        // warp stage: REDUX value max + ballot; winning lane writes partials
        unsigned wmax = __reduce_max_sync(0xffffffffu, __float_as_uint(lv));
        unsigned wm = __ballot_sync(0xffffffffu, __float_as_uint(lv) == wmax);
        const int p = s & 1;
        if (lane == __ffs(wm) - 1) { s_v[p][w] = __uint_as_float(wmax); s_i[p][w] = li; }
        __syncthreads();
        // block stage: REDUX over 8 partials (mirrored quarters)
        float v2 = s_v[p][lane & 7];
        int   i2 = s_i[p][lane & 7];
        unsigned bmax = __reduce_max_sync(0xffffffffu, __float_as_uint(v2));
        unsigned m2 = __ballot_sync(0xffffffffu, __float_as_uint(v2) == bmax);
        far = __shfl_sync(0xffffffffu, i2, __ffs(m2) - 1);
    }
}

// ---------------- ball query + gather (one warp per (b,s)) ----------------
__global__ __launch_bounds__(256) void ball_gather_kernel(const float* __restrict__ xyz,
                                                          const float* __restrict__ points)
{
    const int w    = blockIdx.x * 8 + (threadIdx.x >> 5);
    const int lane = threadIdx.x & 31;
    const int b = w >> 9;
    const int s = w & 511;

    const float* X  = xyz + (size_t)b * 3 * NPTS;
    const float* Yc = X + NPTS;
    const float* Z  = X + 2 * NPTS;

    const float cx = g_newxyz[(b * NPOINT + s) * 3 + 0];
    const float cy = g_newxyz[(b * NPOINT + s) * 3 + 1];
    const float cz = g_newxyz[(b * NPOINT + s) * 3 + 2];
    const float cc = __fadd_rn(__fadd_rn(__fmul_rn(cx, cx), __fmul_rn(cy, cy)),
                               __fmul_rn(cz, cz));
    const float r2 = 0.04f;

    __shared__ int nbr_s[8][NSAMPLE];
    int* nbr = nbr_s[threadIdx.x >> 5];

    int found = 0;
    for (int base = 0; base < NPTS; base += 32) {
        int   j  = base + lane;
        float xj = X[j], yj = Yc[j], zj = Z[j];
        float dot = fmaf(cz, zj, fmaf(cy, yj, __fmul_rn(cx, xj)));
        float pp  = __fadd_rn(__fadd_rn(__fmul_rn(xj, xj), __fmul_rn(yj, yj)),
                              __fmul_rn(zj, zj));
        float d   = __fadd_rn(__fadd_rn(__fmul_rn(-2.0f, dot), cc), pp);
        bool in   = !(d > r2);
        unsigned m = __ballot_sync(0xffffffffu, in);
        int pos = found + __popc(m & ((1u << lane) - 1u));
        if (in && pos < NSAMPLE) nbr[pos] = j;
        found += __popc(m);
        if (found >= NSAMPLE) break;
    }
    __syncwarp();
    if (found > NSAMPLE) found = NSAMPLE;
    int j0 = nbr[0];
    int j  = (lane < found) ? nbr[lane] : j0;

    const int t = (b * NPOINT + s) * NSAMPLE + lane;
    g_X0[0u * NT + t] = X[j]  - cx;
    g_X0[1u * NT + t] = Yc[j] - cy;
    g_X0[2u * NT + t] = Z[j]  - cz;
    const float* P = points + (size_t)b * 64 * NPTS;
    #pragma unroll 4
    for (int d = 0; d < 64; d++) {
        g_X0[(size_t)(3 + d) * NT + t] = P[(size_t)d * NPTS + j];
    }
}

// ---------------- fused layer GEMM: f32x2, double-buffered staging --------
#define CCH 12
template<int CIN, bool BNIN, int LAYER>
__global__ __launch_bounds__(256, 2) void layer_kernel(const float* __restrict__ W,
                                                       const float* __restrict__ bias)
{
    const float* Xin  = (LAYER == 0) ? g_X0 : (LAYER == 1) ? g_Y0 : g_Y1;
    float*       Yout = (LAYER == 0) ? g_Y0 : (LAYER == 1) ? g_Y1 : g_Y2;

    __shared__ __align__(16) float WsT[CIN * 64];       // [c][o]
    __shared__ float bs2[64];
    __shared__ __align__(16) float Xs[2][CCH * 256];    // double buffer
    __shared__ float sc[CIN];
    __shared__ float sh[CIN];

    const int tid   = threadIdx.x;
    const int tx    = tid & 31;
    const int wp    = tid >> 5;
    const int obase = blockIdx.y * 64;
    const int tbase = blockIdx.x * 256;

    const float* Wg = W + (size_t)obase * CIN;
    for (int i = tid; i < 64 * CIN; i += 256) {
        int o = i & 63, c = i >> 6;
        WsT[c * 64 + o] = Wg[o * CIN + c];
    }
    for (int i = tid; i < 64; i += 256) bs2[i] = bias[obase + i];
    if (BNIN) {
        for (int i = tid; i < CIN; i += 256) { sc[i] = g_scale[i]; sh[i] = g_shift[i]; }
    }
    __syncthreads();   // sc/sh/bs2/WsT visible before any consumer

    u64 acc2[4][8];

    auto stage = [&](int cbase, int cn, float* buf) {
        for (int e = tid; e < cn * 64; e += 256) {
            int cc   = e >> 6;
            int col4 = (e & 63) << 2;
            float4 v = *reinterpret_cast<const float4*>(
                Xin + (size_t)(cbase + cc) * NT + tbase + col4);
            if (BNIN) {
                float s = sc[cbase + cc], h = sh[cbase + cc];
                v.x = fmaxf(0.f, fmaf(v.x, s, h));
                v.y = fmaxf(0.f, fmaf(v.y, s, h));
                v.z = fmaxf(0.f, fmaf(v.z, s, h));
                v.w = fmaxf(0.f, fmaf(v.w, s, h));
            }
            *reinterpret_cast<float4*>(buf + cc * 256 + col4) = v;
        }
    };

    {
        int cn0 = (CIN < CCH) ? CIN : CCH;
        stage(0, cn0, Xs[0]);
    }
    #pragma unroll
    for (int j = 0; j < 8; j++) {
        float b0 = bs2[wp * 8 + j];
        u64 bb = pk2(b0, b0);
        #pragma unroll
        for (int k = 0; k < 4; k++) acc2[k][j] = bb;
    }
    __syncthreads();   // Xs[0] staged by all threads

    int ib = 0;
    for (int c0 = 0; c0 < CIN; c0 += CCH, ib ^= 1) {
        const int cn = (CIN - c0 < CCH) ? (CIN - c0) : CCH;
        if (c0 + CCH < CIN) {
            int cn1 = (CIN - c0 - CCH < CCH) ? (CIN - c0 - CCH) : CCH;
            stage(c0 + CCH, cn1, Xs[ib ^ 1]);
        }
        const float* xb = Xs[ib];
        for (int cc = 0; cc < cn; cc++) {
            u64 x2[4];
            #pragma unroll
            for (int k = 0; k < 4; k++)
                x2[k] = *reinterpret_cast<const u64*>(&xb[cc * 256 + 64 * k + 2 * tx]);
            float4 wA = *reinterpret_cast<const float4*>(&WsT[(c0 + cc) * 64 + wp * 8]);
            float4 wB = *reinterpret_cast<const float4*>(&WsT[(c0 + cc) * 64 + wp * 8 + 4]);
            u64 w2[8] = {pk2(wA.x, wA.x), pk2(wA.y, wA.y), pk2(wA.z, wA.z), pk2(wA.w, wA.w),
                         pk2(wB.x, wB.x), pk2(wB.y, wB.y), pk2(wB.z, wB.z), pk2(wB.w, wB.w)};
            #pragma unroll
            for (int j = 0; j < 8; j++)
                #pragma unroll
                for (int k = 0; k < 4; k++)
                    acc2[k][j] = fma2(w2[j], x2[k], acc2[k][j]);
        }
        __syncthreads();
    }

    #pragma unroll
    for (int j = 0; j < 8; j++) {
        const int o = obase + wp * 8 + j;
        float* yp = Yout + (size_t)o * NT + tbase + 2 * tx;
        #pragma unroll
        for (int k = 0; k < 4; k++)
            *reinterpret_cast<u64*>(yp + 64 * k) = acc2[k][j];
    }

    #pragma unroll
    for (int j = 0; j < 8; j++) {
        float s = 0.f, q = 0.f;
        #pragma unroll
        for (int k = 0; k < 4; k++) {
            float lo, hi; upk2(acc2[k][j], lo, hi);
            s += lo; s += hi;
            q = fmaf(lo, lo, q);
            q = fmaf(hi, hi, q);
        }
        #pragma unroll
        for (int off = 16; off; off >>= 1) {
            s += __shfl_down_sync(0xffffffffu, s, off);
            q += __shfl_down_sync(0xffffffffu, q, off);
        }
        if (tx == 0) {
            const int o = obase + wp * 8 + j;
            g_psum[o * NSTILE + blockIdx.x] = s;
            g_psq [o * NSTILE + blockIdx.x] = q;
        }
    }
}

// ---------------- reduce partials -> BN scale/shift (layers 0,1) ----------
__global__ __launch_bounds__(256) void finalize_kernel(const float* __restrict__ g,
                                                       const float* __restrict__ beta)
{
    const int c = blockIdx.x;
    float s = 0.f, q = 0.f;
    for (int i = threadIdx.x; i < NSTILE; i += 256) {
        s += g_psum[c * NSTILE + i];
        q += g_psq [c * NSTILE + i];
    }
    __shared__ float rs[8], rq[8];
    #pragma unroll
    for (int off = 16; off; off >>= 1) {
        s += __shfl_down_sync(0xffffffffu, s, off);
        q += __shfl_down_sync(0xffffffffu, q, off);
    }
    int w = threadIdx.x >> 5;
    if ((threadIdx.x & 31) == 0) { rs[w] = s; rq[w] = q; }
    __syncthreads();
    if (threadIdx.x == 0) {
        float ts = 0.f, tq = 0.f;
        #pragma unroll
        for (int i = 0; i < 8; i++) { ts += rs[i]; tq += rq[i]; }
        float mu  = ts * (1.0f / NT);
        float var = tq * (1.0f / NT) - mu * mu;
        float rsq = rsqrtf(var + 1e-5f);
        float scv = g[c] * rsq;
        g_scale[c] = scv;
        g_shift[c] = fmaf(-mu, scv, beta[c]);
    }
}

// ---------------- layer-2 BN finalize + BN + ReLU + max over k ------------
__global__ __launch_bounds__(256) void final_kernel(float* __restrict__ out2,
                                                    const float* __restrict__ g,
                                                    const float* __restrict__ beta)
{
    const int bo = blockIdx.x;
    const int b = bo >> 7;
    const int o = bo & 127;
    const int tid  = threadIdx.x;
    const int w    = tid >> 5;
    const int lane = tid & 31;

    __shared__ float rs[8], rq[8];
    __shared__ float s_sc, s_sh;
    {
        float s = 0.f, q = 0.f;
        for (int i = tid; i < NSTILE; i += 256) {
            s += g_psum[o * NSTILE + i];
            q += g_psq [o * NSTILE + i];
        }
        #pragma unroll
        for (int off = 16; off; off >>= 1) {
            s += __shfl_down_sync(0xffffffffu, s, off);
            q += __shfl_down_sync(0xffffffffu, q, off);
        }
        if (lane == 0) { rs[w] = s; rq[w] = q; }
        __syncthreads();
        if (tid == 0) {
            float ts = 0.f, tq = 0.f;
            #pragma unroll
            for (int i = 0; i < 8; i++) { ts += rs[i]; tq += rq[i]; }
            float mu  = ts * (1.0f / NT);
            float var = tq * (1.0f / NT) - mu * mu;
            float rsq = rsqrtf(var + 1e-5f);
            float scv = g[o] * rsq;
            s_sc = scv;
            s_sh = fmaf(-mu, scv, beta[o]);
        }
        __syncthreads();
    }
    const float scv = s_sc;
    const float shv = s_sh;

    const float* p = g_Y2 + (size_t)o * NT + (size_t)b * (NPOINT * NSAMPLE);
    for (int r = 0; r < 64; r++) {
        float v = p[tid + r * 256];
        v = fmaxf(0.f, fmaf(v, scv, shv));
        #pragma unroll
        for (int off = 16; off; off >>= 1)
            v = fmaxf(v, __shfl_down_sync(0xffffffffu, v, off));
        if (lane == 0)
            out2[(b * 128 + o) * NPOINT + (w + 8 * r)] = v;
    }
}

// ---------------- launch ----------------
extern "C" void kernel_launch(void* const* d_in, const int* in_sizes, int n_in,
                              void* d_out, int out_size)
{
    (void)in_sizes; (void)n_in; (void)out_size;
    const float* xyz    = (const float*)d_in[0];
    const float* points = (const float*)d_in[1];
    const float* W0 = (const float*)d_in[2];
    const float* b0 = (const float*)d_in[3];
    const float* g0 = (const float*)d_in[4];
    const float* be0= (const float*)d_in[5];
    const float* W1 = (const float*)d_in[6];
    const float* b1 = (const float*)d_in[7];
    const float* g1 = (const float*)d_in[8];
    const float* be1= (const float*)d_in[9];
    const float* W2 = (const float*)d_in[10];
    const float* b2 = (const float*)d_in[11];
    const float* g2 = (const float*)d_in[12];
    const float* be2= (const float*)d_in[13];

    float* out = (float*)d_out;

    fps_kernel<<<BATCH, 256>>>(xyz, out);
    ball_gather_kernel<<<(BATCH * NPOINT) / 8, 256>>>(xyz, points);

    layer_kernel<67, false, 0><<<dim3(NSTILE, 1), 256>>>(W0, b0);
    finalize_kernel<<<64, 256>>>(g0, be0);

    layer_kernel<64, true, 1><<<dim3(NSTILE, 1), 256>>>(W1, b1);
    finalize_kernel<<<64, 256>>>(g1, be1);

    layer_kernel<64, true, 2><<<dim3(NSTILE, 2), 256>>>(W2, b2);

    final_kernel<<<BATCH * 128, 256>>>(out + BATCH * 3 * NPOINT, g2, be2);
}

// round 16
// speedup vs baseline: 1.0779x; 1.0028x over previous
#include <cuda_runtime.h>

#define NPTS    8192
#define BATCH   8
#define NPOINT  512
#define NSAMPLE 32
#define NT      (BATCH*NPOINT*NSAMPLE)   // 131072 samples
#define NSTILE  512                      // sample tiles of 256 in layer kernels

// ---------------- scratch (device globals; no allocation) ----------------
__device__ float g_X0[67u*NT];    // layer0 input features [c][t]
__device__ float g_Y0[64u*NT];    // layer0 raw output (pre-BN)
__device__ float g_Y1[64u*NT];    // layer1 raw output
__device__ float g_Y2[128u*NT];   // layer2 raw output
__device__ float g_newxyz[BATCH*NPOINT*3];   // (b,s,3) centroids
__device__ float g_psum[128*NSTILE];
__device__ float g_psq [128*NSTILE];
__device__ float g_scale[128];
__device__ float g_shift[128];

// ---------------- packed f32x2 helpers (per-half rounding == scalar ops) ---
typedef unsigned long long u64;
__device__ __forceinline__ u64 pk2(float lo, float hi) {
    u64 r; asm("mov.b64 %0,{%1,%2};" : "=l"(r) : "f"(lo), "f"(hi)); return r;
}
__device__ __forceinline__ void upk2(u64 v, float& lo, float& hi) {
    asm("mov.b64 {%0,%1},%2;" : "=f"(lo), "=f"(hi) : "l"(v));
}
__device__ __forceinline__ u64 add2(u64 a, u64 b) {
    u64 r; asm("add.rn.f32x2 %0,%1,%2;" : "=l"(r) : "l"(a), "l"(b)); return r;
}
__device__ __forceinline__ u64 mul2(u64 a, u64 b) {
    u64 r; asm("mul.rn.f32x2 %0,%1,%2;" : "=l"(r) : "l"(a), "l"(b)); return r;
}
__device__ __forceinline__ u64 fma2(u64 a, u64 b, u64 c) {
    u64 r; asm("fma.rn.f32x2 %0,%1,%2,%3;" : "=l"(r) : "l"(a), "l"(b), "l"(c)); return r;
}

// ---------------- FPS ----------------
// One CTA per batch, 256 threads (8 warps), 32 contiguous points/thread.
// Value reduction via __reduce_max_sync on float bits (nonneg -> u32
// monotone; EXACT). First-index via pair-mask trick: the max tree's pair
// maxes a[j] identify the first PAIR containing lv (16 compares), the even
// mask picks the element within the pair (16 compares) — ~half the alu ops
// of the full 32-element scan, identical first-index semantics.
__global__ __launch_bounds__(256) void fps_kernel(const float* __restrict__ xyz,
                                                  float* __restrict__ out_newxyz)
{
    const int b    = blockIdx.x;
    const int tid  = threadIdx.x;
    const int lane = tid & 31;
    const int w    = tid >> 5;           // 0..7
    const float* X  = xyz + (size_t)b * 3 * NPTS;
    const float* Yc = X + NPTS;
    const float* Z  = X + 2 * NPTS;

    // load 32 contiguous points per thread (8x float4 per coordinate)
    float fx[32], fy[32], fz[32];
    #pragma unroll
    for (int r = 0; r < 8; r++) {
        float4 vx = reinterpret_cast<const float4*>(X )[tid * 8 + r];
        float4 vy = reinterpret_cast<const float4*>(Yc)[tid * 8 + r];
        float4 vz = reinterpret_cast<const float4*>(Z )[tid * 8 + r];
        fx[4*r+0]=vx.x; fx[4*r+1]=vx.y; fx[4*r+2]=vx.z; fx[4*r+3]=vx.w;
        fy[4*r+0]=vy.x; fy[4*r+1]=vy.y; fy[4*r+2]=vy.z; fy[4*r+3]=vy.w;
        fz[4*r+0]=vz.x; fz[4*r+1]=vz.y; fz[4*r+2]=vz.z; fz[4*r+3]=vz.w;
    }
    u64 px2[16], py2[16], pz2[16];
    float dist[32];
    #pragma unroll
    for (int m = 0; m < 16; m++) {
        px2[m] = pk2(fx[2*m], fx[2*m+1]);
        py2[m] = pk2(fy[2*m], fy[2*m+1]);
        pz2[m] = pk2(fz[2*m], fz[2*m+1]);
        dist[2*m] = 1e10f; dist[2*m+1] = 1e10f;
    }

    __shared__ float s_v[2][8];
    __shared__ int   s_i[2][8];

    // ---- init: far = argmax over x (first-index ties). x in [0,1) ----
    int far;
    {
        float lv = fx[0];
        #pragma unroll
        for (int j = 1; j < 32; j++) lv = fmaxf(lv, fx[j]);
        unsigned mask = 0;
        #pragma unroll
        for (int j = 0; j < 32; j++)
            mask |= (fx[j] == lv) ? (1u << j) : 0u;
        int li = tid * 32 + (__ffs(mask) - 1);

        unsigned wmax = __reduce_max_sync(0xffffffffu, __float_as_uint(lv));
        unsigned wm = __ballot_sync(0xffffffffu, __float_as_uint(lv) == wmax);
        if (lane == __ffs(wm) - 1) { s_v[1][w] = __uint_as_float(wmax); s_i[1][w] = li; }
        __syncthreads();
        float v2 = s_v[1][lane & 7];
        int   i2 = s_i[1][lane & 7];
        unsigned bmax = __reduce_max_sync(0xffffffffu, __float_as_uint(v2));
        unsigned m2 = __ballot_sync(0xffffffffu, __float_as_uint(v2) == bmax);
        far = __shfl_sync(0xffffffffu, i2, __ffs(m2) - 1);
    }

    for (int s = 0; s < NPOINT; s++) {
        const float cx = X[far], cy = Yc[far], cz = Z[far];   // L1-resident
        if (tid == 0) {
            out_newxyz[(b * 3 + 0) * NPOINT + s] = cx;
            out_newxyz[(b * 3 + 1) * NPOINT + s] = cy;
            out_newxyz[(b * 3 + 2) * NPOINT + s] = cz;
            g_newxyz[(b * NPOINT + s) * 3 + 0] = cx;
            g_newxyz[(b * NPOINT + s) * 3 + 1] = cy;
            g_newxyz[(b * NPOINT + s) * 3 + 2] = cz;
        }
        const u64 ncx2 = pk2(-cx, -cx);
        const u64 ncy2 = pk2(-cy, -cy);
        const u64 ncz2 = pk2(-cz, -cz);
        #pragma unroll
        for (int m = 0; m < 16; m++) {
            u64 dx2 = add2(px2[m], ncx2);          // rn(px - cx) per half
            u64 dy2 = add2(py2[m], ncy2);
            u64 dz2 = add2(pz2[m], ncz2);
            u64 d2  = fma2(dz2, dz2, fma2(dy2, dy2, mul2(dx2, dx2)));
            float d0, d1; upk2(d2, d0, d1);
            dist[2*m]   = fminf(dist[2*m],   d0);
            dist[2*m+1] = fminf(dist[2*m+1], d1);
        }
        // max tree keeping pair maxes a[16]; then pair-mask first-index
        float a[16];
        #pragma unroll
        for (int j = 0; j < 16; j++) a[j] = fmaxf(dist[2*j], dist[2*j+1]);
        float b0 = fmaxf(fmaxf(a[0], a[1]),  fmaxf(a[2], a[3]));
        float b1 = fmaxf(fmaxf(a[4], a[5]),  fmaxf(a[6], a[7]));
        float b2 = fmaxf(fmaxf(a[8], a[9]),  fmaxf(a[10], a[11]));
        float b3 = fmaxf(fmaxf(a[12], a[13]), fmaxf(a[14], a[15]));
        const float lv = fmaxf(fmaxf(b0, b1), fmaxf(b2, b3));

        unsigned pmask = 0, emask = 0;
        #pragma unroll
        for (int j = 0; j < 16; j++) {
            pmask |= (a[j] == lv)        ? (1u << j) : 0u;  // pair contains lv
            emask |= (dist[2*j] == lv)   ? (1u << j) : 0u;  // even elem == lv
        }
        const int jp = __ffs(pmask) - 1;          // first pair containing lv
        const int li = tid * 32 + 2 * jp + (((emask >> jp) & 1u) ? 0 : 1);

        // warp stage: REDUX value max + ballot; winning lane writes partials
        unsigned wmax = __reduce_max_sync(0xffffffffu, __float_as_uint(lv));
        unsigned wm = __ballot_sync(0xffffffffu, __float_as_uint(lv) == wmax);
        const int p = s & 1;
        if (lane == __ffs(wm) - 1) { s_v[p][w] = __uint_as_float(wmax); s_i[p][w] = li; }
        __syncthreads();
        // block stage: REDUX over 8 partials (mirrored quarters)
        float v2 = s_v[p][lane & 7];
        int   i2 = s_i[p][lane & 7];
        unsigned bmax = __reduce_max_sync(0xffffffffu, __float_as_uint(v2));
        unsigned m2 = __ballot_sync(0xffffffffu, __float_as_uint(v2) == bmax);
        far = __shfl_sync(0xffffffffu, i2, __ffs(m2) - 1);
    }
}

// ---------------- ball query + gather (one warp per (b,s)) ----------------
__global__ __launch_bounds__(256) void ball_gather_kernel(const float* __restrict__ xyz,
                                                          const float* __restrict__ points)
{
    const int w    = blockIdx.x * 8 + (threadIdx.x >> 5);
    const int lane = threadIdx.x & 31;
    const int b = w >> 9;
    const int s = w & 511;

    const float* X  = xyz + (size_t)b * 3 * NPTS;
    const float* Yc = X + NPTS;
    const float* Z  = X + 2 * NPTS;

    const float cx = g_newxyz[(b * NPOINT + s) * 3 + 0];
    const float cy = g_newxyz[(b * NPOINT + s) * 3 + 1];
    const float cz = g_newxyz[(b * NPOINT + s) * 3 + 2];
    const float cc = __fadd_rn(__fadd_rn(__fmul_rn(cx, cx), __fmul_rn(cy, cy)),
                               __fmul_rn(cz, cz));
    const float r2 = 0.04f;

    __shared__ int nbr_s[8][NSAMPLE];
    int* nbr = nbr_s[threadIdx.x >> 5];

    int found = 0;
    for (int base = 0; base < NPTS; base += 32) {
        int   j  = base + lane;
        float xj = X[j], yj = Yc[j], zj = Z[j];
        float dot = fmaf(cz, zj, fmaf(cy, yj, __fmul_rn(cx, xj)));
        float pp  = __fadd_rn(__fadd_rn(__fmul_rn(xj, xj), __fmul_rn(yj, yj)),
                              __fmul_rn(zj, zj));
        float d   = __fadd_rn(__fadd_rn(__fmul_rn(-2.0f, dot), cc), pp);
        bool in   = !(d > r2);
        unsigned m = __ballot_sync(0xffffffffu, in);
        int pos = found + __popc(m & ((1u << lane) - 1u));
        if (in && pos < NSAMPLE) nbr[pos] = j;
        found += __popc(m);
        if (found >= NSAMPLE) break;
    }
    __syncwarp();
    if (found > NSAMPLE) found = NSAMPLE;
    int j0 = nbr[0];
    int j  = (lane < found) ? nbr[lane] : j0;

    const int t = (b * NPOINT + s) * NSAMPLE + lane;
    g_X0[0u * NT + t] = X[j]  - cx;
    g_X0[1u * NT + t] = Yc[j] - cy;
    g_X0[2u * NT + t] = Z[j]  - cz;
    const float* P = points + (size_t)b * 64 * NPTS;
    #pragma unroll 4
    for (int d = 0; d < 64; d++) {
        g_X0[(size_t)(3 + d) * NT + t] = P[(size_t)d * NPTS + j];
    }
}

// ---------------- fused layer GEMM: f32x2, double-buffered staging --------
#define CCH 12
template<int CIN, bool BNIN, int LAYER>
__global__ __launch_bounds__(256, 2) void layer_kernel(const float* __restrict__ W,
                                                       const float* __restrict__ bias)
{
    const float* Xin  = (LAYER == 0) ? g_X0 : (LAYER == 1) ? g_Y0 : g_Y1;
    float*       Yout = (LAYER == 0) ? g_Y0 : (LAYER == 1) ? g_Y1 : g_Y2;

    __shared__ __align__(16) float WsT[CIN * 64];       // [c][o]
    __shared__ float bs2[64];
    __shared__ __align__(16) float Xs[2][CCH * 256];    // double buffer
    __shared__ float sc[CIN];
    __shared__ float sh[CIN];

    const int tid   = threadIdx.x;
    const int tx    = tid & 31;
    const int wp    = tid >> 5;
    const int obase = blockIdx.y * 64;
    const int tbase = blockIdx.x * 256;

    const float* Wg = W + (size_t)obase * CIN;
    for (int i = tid; i < 64 * CIN; i += 256) {
        int o = i & 63, c = i >> 6;
        WsT[c * 64 + o] = Wg[o * CIN + c];
    }
    for (int i = tid; i < 64; i += 256) bs2[i] = bias[obase + i];
    if (BNIN) {
        for (int i = tid; i < CIN; i += 256) { sc[i] = g_scale[i]; sh[i] = g_shift[i]; }
    }
    __syncthreads();   // sc/sh/bs2/WsT visible before any consumer

    u64 acc2[4][8];

    auto stage = [&](int cbase, int cn, float* buf) {
        for (int e = tid; e < cn * 64; e += 256) {
            int cc   = e >> 6;
            int col4 = (e & 63) << 2;
            float4 v = *reinterpret_cast<const float4*>(
                Xin + (size_t)(cbase + cc) * NT + tbase + col4);
            if (BNIN) {
                float s = sc[cbase + cc], h = sh[cbase + cc];
                v.x = fmaxf(0.f, fmaf(v.x, s, h));
                v.y = fmaxf(0.f, fmaf(v.y, s, h));
                v.z = fmaxf(0.f, fmaf(v.z, s, h));
                v.w = fmaxf(0.f, fmaf(v.w, s, h));
            }
            *reinterpret_cast<float4*>(buf + cc * 256 + col4) = v;
        }
    };

    {
        int cn0 = (CIN < CCH) ? CIN : CCH;
        stage(0, cn0, Xs[0]);
    }
    #pragma unroll
    for (int j = 0; j < 8; j++) {
        float b0 = bs2[wp * 8 + j];
        u64 bb = pk2(b0, b0);
        #pragma unroll
        for (int k = 0; k < 4; k++) acc2[k][j] = bb;
    }
    __syncthreads();   // Xs[0] staged by all threads

    int ib = 0;
    for (int c0 = 0; c0 < CIN; c0 += CCH, ib ^= 1) {
        const int cn = (CIN - c0 < CCH) ? (CIN - c0) : CCH;
        if (c0 + CCH < CIN) {
            int cn1 = (CIN - c0 - CCH < CCH) ? (CIN - c0 - CCH) : CCH;
            stage(c0 + CCH, cn1, Xs[ib ^ 1]);
        }
        const float* xb = Xs[ib];
        for (int cc = 0; cc < cn; cc++) {
            u64 x2[4];
            #pragma unroll
            for (int k = 0; k < 4; k++)
                x2[k] = *reinterpret_cast<const u64*>(&xb[cc * 256 + 64 * k + 2 * tx]);
            float4 wA = *reinterpret_cast<const float4*>(&WsT[(c0 + cc) * 64 + wp * 8]);
            float4 wB = *reinterpret_cast<const float4*>(&WsT[(c0 + cc) * 64 + wp * 8 + 4]);
            u64 w2[8] = {pk2(wA.x, wA.x), pk2(wA.y, wA.y), pk2(wA.z, wA.z), pk2(wA.w, wA.w),
                         pk2(wB.x, wB.x), pk2(wB.y, wB.y), pk2(wB.z, wB.z), pk2(wB.w, wB.w)};
            #pragma unroll
            for (int j = 0; j < 8; j++)
                #pragma unroll
                for (int k = 0; k < 4; k++)
                    acc2[k][j] = fma2(w2[j], x2[k], acc2[k][j]);
        }
        __syncthreads();
    }

    #pragma unroll
    for (int j = 0; j < 8; j++) {
        const int o = obase + wp * 8 + j;
        float* yp = Yout + (size_t)o * NT + tbase + 2 * tx;
        #pragma unroll
        for (int k = 0; k < 4; k++)
            *reinterpret_cast<u64*>(yp + 64 * k) = acc2[k][j];
    }

    #pragma unroll
    for (int j = 0; j < 8; j++) {
        float s = 0.f, q = 0.f;
        #pragma unroll
        for (int k = 0; k < 4; k++) {
            float lo, hi; upk2(acc2[k][j], lo, hi);
            s += lo; s += hi;
            q = fmaf(lo, lo, q);
            q = fmaf(hi, hi, q);
        }
        #pragma unroll
        for (int off = 16; off; off >>= 1) {
            s += __shfl_down_sync(0xffffffffu, s, off);
            q += __shfl_down_sync(0xffffffffu, q, off);
        }
        if (tx == 0) {
            const int o = obase + wp * 8 + j;
            g_psum[o * NSTILE + blockIdx.x] = s;
            g_psq [o * NSTILE + blockIdx.x] = q;
        }
    }
}

// ---------------- reduce partials -> BN scale/shift ----------
__global__ __launch_bounds__(256) void finalize_kernel(const float* __restrict__ g,
                                                       const float* __restrict__ beta)
{
    const int c = blockIdx.x;
    float s = 0.f, q = 0.f;
    for (int i = threadIdx.x; i < NSTILE; i += 256) {
        s += g_psum[c * NSTILE + i];
        q += g_psq [c * NSTILE + i];
    }
    __shared__ float rs[8], rq[8];
    #pragma unroll
    for (int off = 16; off; off >>= 1) {
        s += __shfl_down_sync(0xffffffffu, s, off);
        q += __shfl_down_sync(0xffffffffu, q, off);
    }
    int w = threadIdx.x >> 5;
    if ((threadIdx.x & 31) == 0) { rs[w] = s; rq[w] = q; }
    __syncthreads();
    if (threadIdx.x == 0) {
        float ts = 0.f, tq = 0.f;
        #pragma unroll
        for (int i = 0; i < 8; i++) { ts += rs[i]; tq += rq[i]; }
        float mu  = ts * (1.0f / NT);
        float var = tq * (1.0f / NT) - mu * mu;
        float rsq = rsqrtf(var + 1e-5f);
        float scv = g[c] * rsq;
        g_scale[c] = scv;
        g_shift[c] = fmaf(-mu, scv, beta[c]);
    }
}

// ---------------- BN + ReLU + max over k (reads g_scale/g_shift) ----------
__global__ __launch_bounds__(256) void final_kernel(float* __restrict__ out2)
{
    const int bo = blockIdx.x;
    const int b = bo >> 7;
    const int o = bo & 127;
    const int tid  = threadIdx.x;
    const int w    = tid >> 5;
    const int lane = tid & 31;

    const float scv = g_scale[o];
    const float shv = g_shift[o];

    const float* p = g_Y2 + (size_t)o * NT + (size_t)b * (NPOINT * NSAMPLE);
    for (int r = 0; r < 64; r++) {
        float v = p[tid + r * 256];
        v = fmaxf(0.f, fmaf(v, scv, shv));
        #pragma unroll
        for (int off = 16; off; off >>= 1)
            v = fmaxf(v, __shfl_down_sync(0xffffffffu, v, off));
        if (lane == 0)
            out2[(b * 128 + o) * NPOINT + (w + 8 * r)] = v;
    }
}

// ---------------- launch ----------------
extern "C" void kernel_launch(void* const* d_in, const int* in_sizes, int n_in,
                              void* d_out, int out_size)
{
    (void)in_sizes; (void)n_in; (void)out_size;
    const float* xyz    = (const float*)d_in[0];
    const float* points = (const float*)d_in[1];
    const float* W0 = (const float*)d_in[2];
    const float* b0 = (const float*)d_in[3];
    const float* g0 = (const float*)d_in[4];
    const float* be0= (const float*)d_in[5];
    const float* W1 = (const float*)d_in[6];
    const float* b1 = (const float*)d_in[7];
    const float* g1 = (const float*)d_in[8];
    const float* be1= (const float*)d_in[9];
    const float* W2 = (const float*)d_in[10];
    const float* b2 = (const float*)d_in[11];
    const float* g2 = (const float*)d_in[12];
    const float* be2= (const float*)d_in[13];

    float* out = (float*)d_out;

    fps_kernel<<<BATCH, 256>>>(xyz, out);
    ball_gather_kernel<<<(BATCH * NPOINT) / 8, 256>>>(xyz, points);

    layer_kernel<67, false, 0><<<dim3(NSTILE, 1), 256>>>(W0, b0);
    finalize_kernel<<<64, 256>>>(g0, be0);

    layer_kernel<64, true, 1><<<dim3(NSTILE, 1), 256>>>(W1, b1);
    finalize_kernel<<<64, 256>>>(g1, be1);

    layer_kernel<64, true, 2><<<dim3(NSTILE, 2), 256>>>(W2, b2);
    finalize_kernel<<<128, 256>>>(g2, be2);

    final_kernel<<<BATCH * 128, 256>>>(out + BATCH * 3 * NPOINT);
}